// round 12
// baseline (speedup 1.0000x reference)
#include <cuda_runtime.h>
#include <cuda_bf16.h>

// Zim_67430986547716 — bbox mask + Gaussian point mask.
// R12: point-PAIR packing in u16 halves (not pixel pairs).
//  - 4 independent accumulator chains per thread (one per pixel), each only
//    16 updates deep (R8/R11 had 2 chains x 32 deep).
//  - per point-pair: dy from REGISTER (preloaded, 4 LDS.128) + 1 LDS.128 dx
//    + 4 VIADDMNMX = 5 slots per 8 point-pixels.
//  - final per pixel: min(lo,hi) then one exp. bias 30000 on dy for invalid
//    points; |d| clamped to 127 so u16 sums can never overflow.
// Shape: R8's proven 1024 quadrant blocks x 256 thr, single wave (8/SM).

#define MASK_N 64
#define NPTS   32
#define NPAIR  16
#define INV_STRIDE (1.0f / 16.0f)
#define INV_2SIG2  (1.0f / 882.0f)   // 2*21*21

__global__ __launch_bounds__(256, 8)
void zim_masks_kernel(const float* __restrict__ boxes,
                      const float* __restrict__ pts,
                      float* __restrict__ bbox_out,
                      float* __restrict__ point_out)
{
    // sdyp[row][k]: u16x2 = (dy2+bias) of point 2k | point 2k+1   (2KB)
    // sdxp[k][col]: u16x2 = dx2 of point 2k | point 2k+1 at col   (4KB)
    __shared__ __align__(16) unsigned int sdyp[32 * NPAIR];
    __shared__ __align__(16) unsigned int sdxp[NPAIR * 64];

    const int b      = blockIdx.x;
    const int quad   = blockIdx.y;              // 0..3
    const int i_base = (quad >> 1) << 5;        // 0 or 32
    const int j_base = (quad & 1) << 5;         // 0 or 32
    const int tid    = threadIdx.x;

    // ---- bbox bounds: one LDG.128, uniform ----
    const float4 bx = __ldg(&reinterpret_cast<const float4*>(boxes)[b]);
    const int xmin_i = max((int)floorf(fminf(bx.x, bx.z) * INV_STRIDE), 0);
    const int ymin_i = max((int)floorf(fminf(bx.y, bx.w) * INV_STRIDE), 0);
    const int xmax_i = min((int)floorf(fmaxf(bx.x, bx.z) * INV_STRIDE) + 1, MASK_N);
    const int ymax_i = min((int)floorf(fmaxf(bx.y, bx.w) * INV_STRIDE) + 1, MASK_N);

    // ---- prologue: thread (k, g) loads point-pair k once (coalesced float4) ----
    {
        const int k = tid & 15;                 // point pair
        const int g = tid >> 4;                 // group 0..15
        const float4 pp = __ldg(&reinterpret_cast<const float4*>(pts)[b * NPAIR + k]);
        const int px0 = (int)floorf(pp.x * INV_STRIDE);
        const int py0 = (int)floorf(pp.y * INV_STRIDE);
        const int px1 = (int)floorf(pp.z * INV_STRIDE);
        const int py1 = (int)floorf(pp.w * INV_STRIDE);
        const int bias0 = ((px0 >= 0) & (py0 >= 0) & (px0 < MASK_N) & (py0 < MASK_N)) ? 0 : 30000;
        const int bias1 = ((px1 >= 0) & (py1 >= 0) & (px1 < MASK_N) & (py1 < MASK_N)) ? 0 : 30000;

        // dx entries: cols 4g..4g+3 of this quadrant
        #pragma unroll
        for (int t = 0; t < 4; t++) {
            const int j = j_base + (g << 2) + t;
            const int a0 = min(abs(j - px0), 127);
            const int a1 = min(abs(j - px1), 127);
            sdxp[k * 64 + (g << 2) + t] =
                (unsigned int)(a0 * a0) | ((unsigned int)(a1 * a1) << 16);
        }
        // dy entries: rows 2g, 2g+1 of this quadrant
        #pragma unroll
        for (int r = 0; r < 2; r++) {
            const int row = (g << 1) + r;
            const int i = i_base + row;
            const int a0 = min(abs(i - py0), 127);
            const int a1 = min(abs(i - py1), 127);
            sdyp[row * NPAIR + k] =
                (unsigned int)(a0 * a0 + bias0) | ((unsigned int)(a1 * a1 + bias1) << 16);
        }
    }
    __syncthreads();

    // ---- per-thread: 1 row x 4 cols; dy in registers, dx streamed ----
    const int il = tid >> 3;            // 0..31 local row
    const int cg = tid & 7;             // col group: cols 4*cg..4*cg+3

    // preload this row's 16 dy pair-words (4 LDS.128, warp-broadcast)
    unsigned int dyr[NPAIR];
    {
        const uint4* dy4 = reinterpret_cast<const uint4*>(&sdyp[il * NPAIR]);
        #pragma unroll
        for (int q = 0; q < 4; q++) {
            const uint4 v = dy4[q];
            dyr[q * 4 + 0] = v.x; dyr[q * 4 + 1] = v.y;
            dyr[q * 4 + 2] = v.z; dyr[q * 4 + 3] = v.w;
        }
    }

    unsigned int a0 = 0xFFFFFFFFu, a1 = 0xFFFFFFFFu;
    unsigned int a2 = 0xFFFFFFFFu, a3 = 0xFFFFFFFFu;

    const unsigned int* dxp = &sdxp[cg << 2];
    #pragma unroll
    for (int k = 0; k < NPAIR; k++) {
        const uint4 dx = *reinterpret_cast<const uint4*>(dxp + k * 64);
        const unsigned int dy = dyr[k];
        a0 = __viaddmin_u16x2(dy, dx.x, a0);
        a1 = __viaddmin_u16x2(dy, dx.y, a1);
        a2 = __viaddmin_u16x2(dy, dx.z, a2);
        a3 = __viaddmin_u16x2(dy, dx.w, a3);
    }

    // ---- per pixel: min of the two point halves, then one exp ----
    const unsigned int m0 = min(a0 & 0xFFFFu, a0 >> 16);
    const unsigned int m1 = min(a1 & 0xFFFFu, a1 >> 16);
    const unsigned int m2 = min(a2 & 0xFFFFu, a2 >> 16);
    const unsigned int m3 = min(a3 & 0xFFFFu, a3 >> 16);
    const float g0 = __expf((float)m0 * -INV_2SIG2);
    const float g1 = __expf((float)m1 * -INV_2SIG2);
    const float g2 = __expf((float)m2 * -INV_2SIG2);
    const float g3 = __expf((float)m3 * -INV_2SIG2);

    // ---- stores ----
    const int i = i_base + il;
    const int j = j_base + (cg << 2);
    const size_t base = (size_t)b * (MASK_N * MASK_N) + (size_t)i * MASK_N + j;

    *reinterpret_cast<float4*>(point_out + base) = make_float4(g0, g1, g2, g3);

    const bool inY = (i >= ymin_i) & (i < ymax_i);
    float4 bv;
    bv.x = (inY & (j + 0 >= xmin_i) & (j + 0 < xmax_i)) ? 1.f : 0.f;
    bv.y = (inY & (j + 1 >= xmin_i) & (j + 1 < xmax_i)) ? 1.f : 0.f;
    bv.z = (inY & (j + 2 >= xmin_i) & (j + 2 < xmax_i)) ? 1.f : 0.f;
    bv.w = (inY & (j + 3 >= xmin_i) & (j + 3 < xmax_i)) ? 1.f : 0.f;
    *reinterpret_cast<float4*>(bbox_out + base) = bv;
}

extern "C" void kernel_launch(void* const* d_in, const int* in_sizes, int n_in,
                              void* d_out, int out_size) {
    const float* boxes = (const float*)d_in[0];   // 256*4
    const float* pts   = (const float*)d_in[1];   // 256*32*2
    float* out = (float*)d_out;                   // 2 * 256*64*64
    const int B = in_sizes[0] / 4;                // 256
    float* bbox_out  = out;
    float* point_out = out + (size_t)B * MASK_N * MASK_N;
    dim3 grid(B, 4);
    zim_masks_kernel<<<grid, 256>>>(boxes, pts, bbox_out, point_out);
}